// round 11
// baseline (speedup 1.0000x reference)
#include <cuda_runtime.h>
#include <cuda_fp16.h>
#include <cstdint>

// Problem constants
#define B_DIM 32
#define N_DIM 2048
#define F_DIM 512
#define K_DIM 256
#define D_DIM 1024
#define M_MAIN (B_DIM * N_DIM)   // 65536

// __device__ scratch (no cudaMalloc allowed anywhere).
__device__ float  g_cbuf[N_DIM * D_DIM];   // city embedding c[N, D]  (8 MB)
__device__ __half g_wf16[D_DIM * F_DIM];   // fp16 W_feat             (1 MB)
__device__ __half g_st16[N_DIM * K_DIM];   // fp16 static             (1 MB)
__device__ __half g_wc16[D_DIM * K_DIM];   // fp16 W_city             (0.5 MB)

// ---------------------------------------------------------------------------
// helpers
// ---------------------------------------------------------------------------
__device__ __forceinline__ uint32_t smem_u32(const void* p) {
    uint32_t a;
    asm("{ .reg .u64 t; cvta.to.shared.u64 t, %1; cvt.u32.u64 %0, t; }"
        : "=r"(a) : "l"(p));
    return a;
}

__device__ __forceinline__ void cp_async16(uint32_t dst, const void* src) {
    asm volatile("cp.async.cg.shared.global [%0], [%1], 16;"
                 :: "r"(dst), "l"(src) : "memory");
}

__device__ __forceinline__ void mma_f16(float& c0, float& c1, float& c2, float& c3,
                                        uint32_t a0, uint32_t a1, uint32_t a2, uint32_t a3,
                                        uint32_t b0, uint32_t b1) {
    asm volatile(
        "mma.sync.aligned.m16n8k16.row.col.f32.f16.f16.f32 "
        "{%0,%1,%2,%3}, {%4,%5,%6,%7}, {%8,%9}, {%0,%1,%2,%3};"
        : "+f"(c0), "+f"(c1), "+f"(c2), "+f"(c3)
        : "r"(a0), "r"(a1), "r"(a2), "r"(a3), "r"(b0), "r"(b1));
}

// ---------------------------------------------------------------------------
// fp32 -> fp16 pre-pass for the three weight tensors (one launch).
// ---------------------------------------------------------------------------
#define WF_N4 (D_DIM * F_DIM / 4)   // 131072
#define ST_N4 (N_DIM * K_DIM / 4)   // 131072
#define WC_N4 (D_DIM * K_DIM / 4)   // 65536
__global__ __launch_bounds__(256) void f2h3_kernel(
    const float* __restrict__ s1, __half* __restrict__ d1,
    const float* __restrict__ s2, __half* __restrict__ d2,
    const float* __restrict__ s3, __half* __restrict__ d3)
{
    int i = blockIdx.x * 1024 + threadIdx.x;
    #pragma unroll
    for (int s = 0; s < 4; s++) {
        int idx = i + s * 256;
        const float* src; __half* dst; int off;
        if (idx < WF_N4)                      { src = s1; dst = d1; off = idx; }
        else if (idx < WF_N4 + ST_N4)         { src = s2; dst = d2; off = idx - WF_N4; }
        else if (idx < WF_N4 + ST_N4 + WC_N4) { src = s3; dst = d3; off = idx - WF_N4 - ST_N4; }
        else continue;
        float4 v = ((const float4*)src)[off];
        __half2 h0 = __floats2half2_rn(v.x, v.y);
        __half2 h1 = __floats2half2_rn(v.z, v.w);
        uint2 u;
        u.x = *(uint32_t*)&h0;
        u.y = *(uint32_t*)&h1;
        ((uint2*)dst)[off] = u;
    }
}

// ---------------------------------------------------------------------------
// Shared tiling constants (fp16 operands, fp32 accum)
// 36-word SMEM row stride -> conflict-free fragment LDS (bank = 4g+t+8ks).
// ---------------------------------------------------------------------------
#define STRIDE_W 36                          // uint32 words per SMEM row (64 halves + pad)

// --- city kernel tiling (proven R8 config: 128x128 tiles, 3-stage) ---
#define BM_T 128
#define BN_T 128
#define BK_T 64
#define A_WORDS (BM_T * STRIDE_W)            // 4608
#define B_WORDS (BN_T * STRIDE_W)            // 4608
#define STAGE_WORDS (A_WORDS + B_WORDS)      // 9216
#define NSTAGE 3
#define SMEM_CITY_BYTES (NSTAGE * STAGE_WORDS * 4)  // 110592

// --- main fused kernel layout ---
#define MROW 128                             // rows per CTA
#define MCH 64                               // total chunks = 8 bn * 8 k
#define MBSTG_W (128 * STRIDE_W)             // 4608 words per B stage
#define MB_NSTG 3
#define MA_BASE_W (MB_NSTG * MBSTG_W)        // 13824 (A region start, word)
#define MA_CH_W 4608                         // words per A K-chunk (128 rows)
#define MPART_W (MA_BASE_W + 8 * MA_CH_W)    // 50688 partial[2][128] float2
#define MSUMS_W (MPART_W + 512)              // 51200 sums/stats[128] float2
#define MSMEM_BYTES ((MSUMS_W + 256) * 4)    // 205824 bytes

// ---------------------------------------------------------------------------
// City GEMM (fp16 mma): g_cbuf[m*D + n] = static @ W_city^T + b_city
// ---------------------------------------------------------------------------
__global__ __launch_bounds__(256, 2) void city_gemm(
    const __half* __restrict__ A,    // [N_DIM, K_DIM]
    const __half* __restrict__ W,    // [D_DIM, K_DIM]
    const float* __restrict__ bias)  // [D_DIM]
{
    constexpr int KD = K_DIM;
    constexpr int NCHUNK = KD / BK_T;   // 4

    extern __shared__ uint32_t smem[];
    const int tid  = threadIdx.x;
    const int wid  = tid >> 5;
    const int lane = tid & 31;
    const int wm   = wid & 3;
    const int wn   = wid >> 2;
    const int g    = lane >> 2;
    const int t    = lane & 3;

    const int bm = blockIdx.y * BM_T;
    const int bn = blockIdx.x * BN_T;

    const __half* Arow = A + (size_t)bm * KD;
    const __half* Wrow = W + (size_t)bn * KD;
    const uint32_t smem_b = smem_u32(smem);

    float acc[2][8][4];
    #pragma unroll
    for (int i = 0; i < 2; i++)
        #pragma unroll
        for (int j = 0; j < 8; j++)
            #pragma unroll
            for (int c = 0; c < 4; c++) acc[i][j][c] = 0.0f;

    auto prefetch = [&](int k0, int buf) {
        const uint32_t a_s = smem_b + (uint32_t)(buf * STAGE_WORDS) * 4u;
        const uint32_t b_s = a_s + A_WORDS * 4u;
        #pragma unroll
        for (int s = 0; s < 4; s++) {
            int id = tid + s * 256;
            int r  = id >> 3;
            int c16 = id & 7;
            cp_async16(a_s + (uint32_t)(r * 144 + c16 * 16),
                       Arow + (size_t)r * KD + k0 + c16 * 8);
        }
        #pragma unroll
        for (int s = 0; s < 4; s++) {
            int id = tid + s * 256;
            int r  = id >> 3;
            int c16 = id & 7;
            cp_async16(b_s + (uint32_t)(r * 144 + c16 * 16),
                       Wrow + (size_t)r * KD + k0 + c16 * 8);
        }
    };

    prefetch(0, 0);
    asm volatile("cp.async.commit_group;" ::: "memory");
    prefetch(BK_T, 1);
    asm volatile("cp.async.commit_group;" ::: "memory");

    #pragma unroll
    for (int k = 0; k < NCHUNK; k++) {
        if (k + 1 < NCHUNK) {
            asm volatile("cp.async.wait_group 1;" ::: "memory");
        } else {
            asm volatile("cp.async.wait_group 0;" ::: "memory");
        }
        __syncthreads();
        if (k + 2 < NCHUNK) {
            prefetch((k + 2) * BK_T, (k + 2) % NSTAGE);
            asm volatile("cp.async.commit_group;" ::: "memory");
        }

        const uint32_t* As32 = smem + (k % NSTAGE) * STAGE_WORDS;
        const uint32_t* Bs32 = As32 + A_WORDS;

        #pragma unroll
        for (int ks = 0; ks < 4; ks++) {
            uint32_t af[2][4];
            #pragma unroll
            for (int i = 0; i < 2; i++) {
                const uint32_t* ap = As32 + (wm * 32 + i * 16 + g) * STRIDE_W + ks * 8 + t;
                af[i][0] = ap[0];
                af[i][1] = ap[8 * STRIDE_W];
                af[i][2] = ap[4];
                af[i][3] = ap[8 * STRIDE_W + 4];
            }
            #pragma unroll
            for (int j = 0; j < 8; j++) {
                const uint32_t* bp = Bs32 + (wn * 64 + j * 8 + g) * STRIDE_W + ks * 8 + t;
                uint32_t b0 = bp[0];
                uint32_t b1 = bp[4];
                #pragma unroll
                for (int i = 0; i < 2; i++)
                    mma_f16(acc[i][j][0], acc[i][j][1], acc[i][j][2], acc[i][j][3],
                            af[i][0], af[i][1], af[i][2], af[i][3], b0, b1);
            }
        }
    }

    #pragma unroll
    for (int i = 0; i < 2; i++) {
        #pragma unroll
        for (int half = 0; half < 2; half++) {
            const int m = bm + wm * 32 + i * 16 + half * 8 + g;
            float* orow = g_cbuf + (size_t)m * D_DIM;
            #pragma unroll
            for (int j = 0; j < 8; j++) {
                const int n = bn + wn * 64 + j * 8 + 2 * t;
                float2 o;
                o.x = acc[i][j][half * 2 + 0] + __ldg(bias + n);
                o.y = acc[i][j][half * 2 + 1] + __ldg(bias + n + 1);
                *(float2*)(orow + n) = o;
            }
        }
    }
}

// ---------------------------------------------------------------------------
// Main fused kernel (no cluster): each CTA owns 128 rows x full D=1024.
//  - A (128x512) converted fp32->fp16 once into resident SMEM (chunk layout)
//  - loops 8 N-tiles of W; B streamed via 3-stage cp.async (64 chunks total)
//  - epilogue per N-tile: bias+leaky+gate, pre-LN STG to out, row-stat accum
//  - final: block-local LN stats, normalize pass re-reading out (L2-hot)
// ---------------------------------------------------------------------------
__global__ __launch_bounds__(256, 1) void main_fused(
    const float* __restrict__ input,  // [M_MAIN, F_DIM] fp32
    const __half* __restrict__ W,     // [D_DIM, F_DIM] fp16
    const float* __restrict__ bias,   // [D_DIM]
    const float* __restrict__ gamma,  // [D_DIM]
    const float* __restrict__ beta,   // [D_DIM]
    float* __restrict__ out)          // [M_MAIN, D_DIM]
{
    extern __shared__ uint32_t smem[];
    const int tid  = threadIdx.x;
    const int wid  = tid >> 5;
    const int lane = tid & 31;
    const int wm   = wid & 3;        // warp row  (32 rows each)
    const int wn   = wid >> 2;       // warp col  (64 cols of the 128-wide N tile)
    const int g    = lane >> 2;
    const int t    = lane & 3;
    const int bm   = blockIdx.x * MROW;
    const uint32_t smem_b = smem_u32(smem);

    float2* partial = (float2*)(smem + MPART_W);   // [2][128]
    float2* sums    = (float2*)(smem + MSUMS_W);   // [128] (later stats)

    if (tid < 128) { float2 z; z.x = 0.0f; z.y = 0.0f; sums[tid] = z; }

    auto prefetchB = [&](int ch) {
        const int bn2 = ch >> 3, k2 = ch & 7, stg = ch % 3;
        const uint32_t bs = smem_b + (uint32_t)stg * (MBSTG_W * 4u);
        const __half* Wb = W + (size_t)(bn2 * 128) * F_DIM + k2 * 64;
        #pragma unroll
        for (int s = 0; s < 4; s++) {
            int id = tid + s * 256;
            int r = id >> 3, c16 = id & 7;
            cp_async16(bs + (uint32_t)(r * 144 + c16 * 16),
                       Wb + (size_t)r * F_DIM + c16 * 8);
        }
    };

    prefetchB(0);
    asm volatile("cp.async.commit_group;" ::: "memory");
    prefetchB(1);
    asm volatile("cp.async.commit_group;" ::: "memory");

    // A load + fp16 convert into resident SMEM (overlaps with B cp.async).
    {
        const float* Arow = input + (size_t)bm * F_DIM;
        #pragma unroll 8
        for (int s = 0; s < 64; s++) {
            int id = s * 256 + tid;
            int r = id >> 7, k4 = id & 127;
            float4 v = *(const float4*)(Arow + (size_t)r * F_DIM + k4 * 4);
            __half2 h0 = __floats2half2_rn(v.x, v.y);
            __half2 h1 = __floats2half2_rn(v.z, v.w);
            uint2 u;
            u.x = *(uint32_t*)&h0;
            u.y = *(uint32_t*)&h1;
            int c = k4 >> 4, w = (k4 & 15) * 2;
            *(uint2*)(smem + MA_BASE_W + c * MA_CH_W + r * STRIDE_W + w) = u;
        }
    }

    float acc[2][8][4];
    #pragma unroll
    for (int i2 = 0; i2 < 2; i2++)
        #pragma unroll
        for (int j = 0; j < 8; j++)
            #pragma unroll
            for (int c = 0; c < 4; c++) acc[i2][j][c] = 0.0f;

    #pragma unroll 1
    for (int i = 0; i < MCH; i++) {
        // My chunk-i group done...
        if (i + 1 < MCH) {
            asm volatile("cp.async.wait_group 1;" ::: "memory");
        } else {
            asm volatile("cp.async.wait_group 0;" ::: "memory");
        }
        // ...then one barrier: chunk-i data visible to all, all warps past
        // compute of i-1 (stage (i+2)%3 == (i-1)%3 free). Also covers the
        // one-time A-load stores on i==0.
        __syncthreads();

        if (i + 2 < MCH) {
            prefetchB(i + 2);
            asm volatile("cp.async.commit_group;" ::: "memory");
        }

        const uint32_t* As32 = smem + MA_BASE_W + (i & 7) * MA_CH_W;
        const uint32_t* Bs32 = smem + (i % 3) * MBSTG_W;

        #pragma unroll
        for (int ks = 0; ks < 4; ks++) {
            uint32_t af[2][4];
            #pragma unroll
            for (int i2 = 0; i2 < 2; i2++) {
                const uint32_t* ap = As32 + (wm * 32 + i2 * 16 + g) * STRIDE_W + ks * 8 + t;
                af[i2][0] = ap[0];
                af[i2][1] = ap[8 * STRIDE_W];
                af[i2][2] = ap[4];
                af[i2][3] = ap[8 * STRIDE_W + 4];
            }
            #pragma unroll
            for (int j = 0; j < 8; j++) {
                const uint32_t* bp = Bs32 + (wn * 64 + j * 8 + g) * STRIDE_W + ks * 8 + t;
                uint32_t b0 = bp[0];
                uint32_t b1 = bp[4];
                #pragma unroll
                for (int i2 = 0; i2 < 2; i2++)
                    mma_f16(acc[i2][j][0], acc[i2][j][1], acc[i2][j][2], acc[i2][j][3],
                            af[i2][0], af[i2][1], af[i2][2], af[i2][3], b0, b1);
            }
        }

        if ((i & 7) == 7) {
            // Epilogue for N-tile bn: bias + leaky + gate, pre-LN store,
            // per-row partial stats; then accumulate into running sums.
            const int bn = (i >> 3) * 128;
            #pragma unroll
            for (int i2 = 0; i2 < 2; i2++) {
                #pragma unroll
                for (int half = 0; half < 2; half++) {
                    const int rl = wm * 32 + i2 * 16 + half * 8 + g;
                    const int m = bm + rl;
                    const float* gate = g_cbuf + (size_t)(m & (N_DIM - 1)) * D_DIM;
                    float* orow = out + (size_t)m * D_DIM;
                    float s = 0.0f, ss = 0.0f;
                    #pragma unroll
                    for (int j = 0; j < 8; j++) {
                        const int n = bn + wn * 64 + j * 8 + 2 * t;
                        float2 bv = *(const float2*)(bias + n);
                        float2 gv = *(const float2*)(gate + n);
                        float v0 = acc[i2][j][half * 2 + 0] + bv.x;
                        float v1 = acc[i2][j][half * 2 + 1] + bv.y;
                        v0 = (v0 >= 0.0f) ? v0 : 0.2f * v0;
                        v1 = (v1 >= 0.0f) ? v1 : 0.2f * v1;
                        v0 *= gv.x;
                        v1 *= gv.y;
                        float2 o; o.x = v0; o.y = v1;
                        *(float2*)(orow + n) = o;
                        s += v0 + v1;
                        ss += v0 * v0 + v1 * v1;
                        acc[i2][j][half * 2 + 0] = 0.0f;   // reset for next tile
                        acc[i2][j][half * 2 + 1] = 0.0f;
                    }
                    s  += __shfl_xor_sync(0xFFFFFFFFu, s, 1);
                    ss += __shfl_xor_sync(0xFFFFFFFFu, ss, 1);
                    s  += __shfl_xor_sync(0xFFFFFFFFu, s, 2);
                    ss += __shfl_xor_sync(0xFFFFFFFFu, ss, 2);
                    if (t == 0) {
                        float2 p; p.x = s; p.y = ss;
                        partial[wn * 128 + rl] = p;
                    }
                }
            }
            __syncthreads();
            if (tid < 128) {
                float2 a = partial[tid];
                float2 b = partial[128 + tid];
                float2 sv = sums[tid];
                sv.x += a.x + b.x;
                sv.y += a.y + b.y;
                sums[tid] = sv;
            }
            // next loop iteration's __syncthreads orders this against reuse
        }
    }

    __syncthreads();
    if (tid < 128) {
        float2 sv = sums[tid];
        const float inv_d = 1.0f / (float)D_DIM;
        float mean = sv.x * inv_d;
        float var  = sv.y * inv_d - mean * mean;
        float2 st; st.x = mean; st.y = rsqrtf(var + 1e-5f);
        sums[tid] = st;   // reuse as stats
    }
    __syncthreads();

    // Normalize pass: rows [bm, bm+128), thread owns cols [tid*4, tid*4+4).
    // Data was just written by this CTA -> L2-hot (coherent plain loads).
    {
        float4 gm = *(const float4*)(gamma + tid * 4);
        float4 be = *(const float4*)(beta + tid * 4);
        float* ob = out + (size_t)bm * D_DIM + tid * 4;
        #pragma unroll 1
        for (int r = 0; r < MROW; r += 4) {
            float4 v0 = *(float4*)(ob + (size_t)(r + 0) * D_DIM);
            float4 v1 = *(float4*)(ob + (size_t)(r + 1) * D_DIM);
            float4 v2 = *(float4*)(ob + (size_t)(r + 2) * D_DIM);
            float4 v3 = *(float4*)(ob + (size_t)(r + 3) * D_DIM);
            float2 s0 = sums[r + 0];
            float2 s1 = sums[r + 1];
            float2 s2 = sums[r + 2];
            float2 s3 = sums[r + 3];
            v0.x = (v0.x - s0.x) * s0.y * gm.x + be.x;
            v0.y = (v0.y - s0.x) * s0.y * gm.y + be.y;
            v0.z = (v0.z - s0.x) * s0.y * gm.z + be.z;
            v0.w = (v0.w - s0.x) * s0.y * gm.w + be.w;
            v1.x = (v1.x - s1.x) * s1.y * gm.x + be.x;
            v1.y = (v1.y - s1.x) * s1.y * gm.y + be.y;
            v1.z = (v1.z - s1.x) * s1.y * gm.z + be.z;
            v1.w = (v1.w - s1.x) * s1.y * gm.w + be.w;
            v2.x = (v2.x - s2.x) * s2.y * gm.x + be.x;
            v2.y = (v2.y - s2.x) * s2.y * gm.y + be.y;
            v2.z = (v2.z - s2.x) * s2.y * gm.z + be.z;
            v2.w = (v2.w - s2.x) * s2.y * gm.w + be.w;
            v3.x = (v3.x - s3.x) * s3.y * gm.x + be.x;
            v3.y = (v3.y - s3.x) * s3.y * gm.y + be.y;
            v3.z = (v3.z - s3.x) * s3.y * gm.z + be.z;
            v3.w = (v3.w - s3.x) * s3.y * gm.w + be.w;
            *(float4*)(ob + (size_t)(r + 0) * D_DIM) = v0;
            *(float4*)(ob + (size_t)(r + 1) * D_DIM) = v1;
            *(float4*)(ob + (size_t)(r + 2) * D_DIM) = v2;
            *(float4*)(ob + (size_t)(r + 3) * D_DIM) = v3;
        }
    }
}

// ---------------------------------------------------------------------------
extern "C" void kernel_launch(void* const* d_in, const int* in_sizes, int n_in,
                              void* d_out, int out_size)
{
    const float* input  = (const float*)d_in[0];  // [B, N, F]
    const float* stat   = (const float*)d_in[1];  // [N, K]
    const float* W_feat = (const float*)d_in[2];  // [D, F]
    const float* b_feat = (const float*)d_in[3];  // [D]
    const float* W_city = (const float*)d_in[4];  // [D, K]
    const float* b_city = (const float*)d_in[5];  // [D]
    const float* gamma  = (const float*)d_in[6];  // [D]
    const float* beta   = (const float*)d_in[7];  // [D]
    float* out = (float*)d_out;                   // [B, N, D]

    cudaFuncSetAttribute(main_fused,
                         cudaFuncAttributeMaxDynamicSharedMemorySize,
                         MSMEM_BYTES);
    cudaFuncSetAttribute(city_gemm,
                         cudaFuncAttributeMaxDynamicSharedMemorySize,
                         SMEM_CITY_BYTES);

    __half *wf16, *st16, *wc16;
    cudaGetSymbolAddress((void**)&wf16, g_wf16);
    cudaGetSymbolAddress((void**)&st16, g_st16);
    cudaGetSymbolAddress((void**)&wc16, g_wc16);

    // 0) fp32 -> fp16 pre-pass for weights only (input converted in-kernel)
    {
        int tot4 = WF_N4 + ST_N4 + WC_N4;  // 327680
        f2h3_kernel<<<(tot4 + 1023) / 1024, 256>>>(W_feat, wf16, stat, st16,
                                                   W_city, wc16);
    }
    // 1) city embed: g_cbuf = static @ W_city^T + b_city
    {
        dim3 grid(D_DIM / BN_T, N_DIM / BM_T);   // (8, 16)
        city_gemm<<<grid, 256, SMEM_CITY_BYTES>>>(st16, wc16, b_city);
    }
    // 2) main fused: out = LN(leaky(input @ W_feat^T + b) * gate) * gamma + beta
    {
        main_fused<<<M_MAIN / MROW, 256, MSMEM_BYTES>>>(input, wf16, b_feat,
                                                        gamma, beta, out);
    }
}

// round 13
// speedup vs baseline: 2.3397x; 2.3397x over previous
#include <cuda_runtime.h>
#include <cuda_fp16.h>
#include <cstdint>

// Problem constants
#define B_DIM 32
#define N_DIM 2048
#define F_DIM 512
#define K_DIM 256
#define D_DIM 1024
#define M_MAIN (B_DIM * N_DIM)   // 65536
#define NBM 512                  // main grid bm blocks
#define NBN 8                    // main grid bn blocks

// __device__ scratch (no cudaMalloc allowed anywhere).
__device__ float  g_cbuf[N_DIM * D_DIM];   // city embedding c[N, D]  (8 MB)
__device__ __half g_a16[M_MAIN * F_DIM];   // fp16 input              (64 MB)
__device__ __half g_wf16[D_DIM * F_DIM];   // fp16 W_feat             (1 MB)
__device__ __half g_st16[N_DIM * K_DIM];   // fp16 static             (1 MB)
__device__ __half g_wc16[D_DIM * K_DIM];   // fp16 W_city             (0.5 MB)
__device__ float2 g_part[NBM * NBN * 128]; // per-(bm,bn,row) LN partials (4 MB)
__device__ int    g_cnt[NBM];              // arrival counters (zero-init; self-reset)

// ---------------------------------------------------------------------------
// helpers
// ---------------------------------------------------------------------------
__device__ __forceinline__ uint32_t smem_u32(const void* p) {
    uint32_t a;
    asm("{ .reg .u64 t; cvta.to.shared.u64 t, %1; cvt.u32.u64 %0, t; }"
        : "=r"(a) : "l"(p));
    return a;
}

__device__ __forceinline__ void cp_async16(uint32_t dst, const void* src) {
    asm volatile("cp.async.cg.shared.global [%0], [%1], 16;"
                 :: "r"(dst), "l"(src) : "memory");
}

__device__ __forceinline__ void mma_f16(float& c0, float& c1, float& c2, float& c3,
                                        uint32_t a0, uint32_t a1, uint32_t a2, uint32_t a3,
                                        uint32_t b0, uint32_t b1) {
    asm volatile(
        "mma.sync.aligned.m16n8k16.row.col.f32.f16.f16.f32 "
        "{%0,%1,%2,%3}, {%4,%5,%6,%7}, {%8,%9}, {%0,%1,%2,%3};"
        : "+f"(c0), "+f"(c1), "+f"(c2), "+f"(c3)
        : "r"(a0), "r"(a1), "r"(a2), "r"(a3), "r"(b0), "r"(b1));
}

// ---------------------------------------------------------------------------
// fp32 -> fp16 pre-passes
// ---------------------------------------------------------------------------
__global__ __launch_bounds__(256) void f2h_kernel(
    const float* __restrict__ src, __half* __restrict__ dst, int n4)
{
    int i = blockIdx.x * 1024 + threadIdx.x;
    #pragma unroll
    for (int s = 0; s < 4; s++) {
        int idx = i + s * 256;
        if (idx < n4) {
            float4 v = ((const float4*)src)[idx];
            __half2 h0 = __floats2half2_rn(v.x, v.y);
            __half2 h1 = __floats2half2_rn(v.z, v.w);
            uint2 u;
            u.x = *(uint32_t*)&h0;
            u.y = *(uint32_t*)&h1;
            ((uint2*)dst)[idx] = u;
        }
    }
}

#define WF_N4 (D_DIM * F_DIM / 4)   // 131072
#define ST_N4 (N_DIM * K_DIM / 4)   // 131072
#define WC_N4 (D_DIM * K_DIM / 4)   // 65536
__global__ __launch_bounds__(256) void f2h3_kernel(
    const float* __restrict__ s1, __half* __restrict__ d1,
    const float* __restrict__ s2, __half* __restrict__ d2,
    const float* __restrict__ s3, __half* __restrict__ d3)
{
    int i = blockIdx.x * 1024 + threadIdx.x;
    #pragma unroll
    for (int s = 0; s < 4; s++) {
        int idx = i + s * 256;
        const float* src; __half* dst; int off;
        if (idx < WF_N4)                      { src = s1; dst = d1; off = idx; }
        else if (idx < WF_N4 + ST_N4)         { src = s2; dst = d2; off = idx - WF_N4; }
        else if (idx < WF_N4 + ST_N4 + WC_N4) { src = s3; dst = d3; off = idx - WF_N4 - ST_N4; }
        else continue;
        float4 v = ((const float4*)src)[off];
        __half2 h0 = __floats2half2_rn(v.x, v.y);
        __half2 h1 = __floats2half2_rn(v.z, v.w);
        uint2 u;
        u.x = *(uint32_t*)&h0;
        u.y = *(uint32_t*)&h1;
        ((uint2*)dst)[off] = u;
    }
}

// ---------------------------------------------------------------------------
// Tiling constants (fp16 operands, fp32 accum); 36-word SMEM row stride
// -> conflict-free fragment LDS.
// ---------------------------------------------------------------------------
#define BM_T 128
#define BN_T 128
#define BK_T 64
#define STRIDE_W 36
#define A_WORDS (BM_T * STRIDE_W)            // 4608
#define B_WORDS (BN_T * STRIDE_W)            // 4608
#define STAGE_WORDS (A_WORDS + B_WORDS)      // 9216
#define NSTAGE 3
#define SMEM_BYTES (NSTAGE * STAGE_WORDS * 4)  // 110592

// ---------------------------------------------------------------------------
// City GEMM (fp16 mma): g_cbuf[m*D + n] = static @ W_city^T + b_city
// ---------------------------------------------------------------------------
__global__ __launch_bounds__(256, 2) void city_gemm(
    const __half* __restrict__ A,    // [N_DIM, K_DIM]
    const __half* __restrict__ W,    // [D_DIM, K_DIM]
    const float* __restrict__ bias)  // [D_DIM]
{
    constexpr int KD = K_DIM;
    constexpr int NCHUNK = KD / BK_T;   // 4

    extern __shared__ uint32_t smem[];
    const int tid  = threadIdx.x;
    const int wid  = tid >> 5;
    const int lane = tid & 31;
    const int wm   = wid & 3;
    const int wn   = wid >> 2;
    const int g    = lane >> 2;
    const int t    = lane & 3;

    const int bm = blockIdx.y * BM_T;
    const int bn = blockIdx.x * BN_T;

    const __half* Arow = A + (size_t)bm * KD;
    const __half* Wrow = W + (size_t)bn * KD;
    const uint32_t smem_b = smem_u32(smem);

    float acc[2][8][4];
    #pragma unroll
    for (int i = 0; i < 2; i++)
        #pragma unroll
        for (int j = 0; j < 8; j++)
            #pragma unroll
            for (int c = 0; c < 4; c++) acc[i][j][c] = 0.0f;

    auto prefetch = [&](int k0, int buf) {
        const uint32_t a_s = smem_b + (uint32_t)(buf * STAGE_WORDS) * 4u;
        const uint32_t b_s = a_s + A_WORDS * 4u;
        #pragma unroll
        for (int s = 0; s < 4; s++) {
            int id = tid + s * 256;
            int r  = id >> 3;
            int c16 = id & 7;
            cp_async16(a_s + (uint32_t)(r * 144 + c16 * 16),
                       Arow + (size_t)r * KD + k0 + c16 * 8);
        }
        #pragma unroll
        for (int s = 0; s < 4; s++) {
            int id = tid + s * 256;
            int r  = id >> 3;
            int c16 = id & 7;
            cp_async16(b_s + (uint32_t)(r * 144 + c16 * 16),
                       Wrow + (size_t)r * KD + k0 + c16 * 8);
        }
    };

    prefetch(0, 0);
    asm volatile("cp.async.commit_group;" ::: "memory");
    prefetch(BK_T, 1);
    asm volatile("cp.async.commit_group;" ::: "memory");

    #pragma unroll
    for (int k = 0; k < NCHUNK; k++) {
        if (k + 1 < NCHUNK) {
            asm volatile("cp.async.wait_group 1;" ::: "memory");
        } else {
            asm volatile("cp.async.wait_group 0;" ::: "memory");
        }
        __syncthreads();
        if (k + 2 < NCHUNK) {
            prefetch((k + 2) * BK_T, (k + 2) % NSTAGE);
            asm volatile("cp.async.commit_group;" ::: "memory");
        }

        const uint32_t* As32 = smem + (k % NSTAGE) * STAGE_WORDS;
        const uint32_t* Bs32 = As32 + A_WORDS;

        #pragma unroll
        for (int ks = 0; ks < 4; ks++) {
            uint32_t af[2][4];
            #pragma unroll
            for (int i = 0; i < 2; i++) {
                const uint32_t* ap = As32 + (wm * 32 + i * 16 + g) * STRIDE_W + ks * 8 + t;
                af[i][0] = ap[0];
                af[i][1] = ap[8 * STRIDE_W];
                af[i][2] = ap[4];
                af[i][3] = ap[8 * STRIDE_W + 4];
            }
            #pragma unroll
            for (int j = 0; j < 8; j++) {
                const uint32_t* bp = Bs32 + (wn * 64 + j * 8 + g) * STRIDE_W + ks * 8 + t;
                uint32_t b0 = bp[0];
                uint32_t b1 = bp[4];
                #pragma unroll
                for (int i = 0; i < 2; i++)
                    mma_f16(acc[i][j][0], acc[i][j][1], acc[i][j][2], acc[i][j][3],
                            af[i][0], af[i][1], af[i][2], af[i][3], b0, b1);
            }
        }
    }

    #pragma unroll
    for (int i = 0; i < 2; i++) {
        #pragma unroll
        for (int half = 0; half < 2; half++) {
            const int m = bm + wm * 32 + i * 16 + half * 8 + g;
            float* orow = g_cbuf + (size_t)m * D_DIM;
            #pragma unroll
            for (int j = 0; j < 8; j++) {
                const int n = bn + wn * 64 + j * 8 + 2 * t;
                float2 o;
                o.x = acc[i][j][half * 2 + 0] + __ldg(bias + n);
                o.y = acc[i][j][half * 2 + 1] + __ldg(bias + n + 1);
                *(float2*)(orow + n) = o;
            }
        }
    }
}

// ---------------------------------------------------------------------------
// Main GEMM + fused gate + stream-K LayerNorm fixup (no clusters).
// Each CTA: 128x128 tile; epilogue writes gated pre-LN out + per-row partial
// stats; last CTA per row-block (atomic counter) computes stats and
// normalizes the whole 128x1024 block from L2.
// ---------------------------------------------------------------------------
__global__ __launch_bounds__(256, 2) void main_gemm_fused(
    const __half* __restrict__ A,    // [M_MAIN, F_DIM]
    const __half* __restrict__ W,    // [D_DIM, F_DIM]
    const float* __restrict__ bias,  // [D_DIM]
    const float* __restrict__ gamma, // [D_DIM]
    const float* __restrict__ beta,  // [D_DIM]
    float* __restrict__ out)         // [M_MAIN, D_DIM]
{
    constexpr int KD = F_DIM;
    constexpr int NCHUNK = KD / BK_T;   // 8

    extern __shared__ uint32_t smem[];
    const int tid  = threadIdx.x;
    const int wid  = tid >> 5;
    const int lane = tid & 31;
    const int wm   = wid & 3;
    const int wn   = wid >> 2;
    const int g    = lane >> 2;
    const int t    = lane & 3;

    const int bmb = blockIdx.y;          // 0..511
    const int bm = bmb * BM_T;
    const int bn = blockIdx.x * BN_T;

    const __half* Arow = A + (size_t)bm * KD;
    const __half* Wrow = W + (size_t)bn * KD;
    const uint32_t smem_b = smem_u32(smem);

    float acc[2][8][4];
    #pragma unroll
    for (int i = 0; i < 2; i++)
        #pragma unroll
        for (int j = 0; j < 8; j++)
            #pragma unroll
            for (int c = 0; c < 4; c++) acc[i][j][c] = 0.0f;

    auto prefetch = [&](int k0, int buf) {
        const uint32_t a_s = smem_b + (uint32_t)(buf * STAGE_WORDS) * 4u;
        const uint32_t b_s = a_s + A_WORDS * 4u;
        #pragma unroll
        for (int s = 0; s < 4; s++) {
            int id = tid + s * 256;
            int r  = id >> 3;
            int c16 = id & 7;
            cp_async16(a_s + (uint32_t)(r * 144 + c16 * 16),
                       Arow + (size_t)r * KD + k0 + c16 * 8);
        }
        #pragma unroll
        for (int s = 0; s < 4; s++) {
            int id = tid + s * 256;
            int r  = id >> 3;
            int c16 = id & 7;
            cp_async16(b_s + (uint32_t)(r * 144 + c16 * 16),
                       Wrow + (size_t)r * KD + k0 + c16 * 8);
        }
    };

    prefetch(0, 0);
    asm volatile("cp.async.commit_group;" ::: "memory");
    prefetch(BK_T, 1);
    asm volatile("cp.async.commit_group;" ::: "memory");

    #pragma unroll
    for (int k = 0; k < NCHUNK; k++) {
        if (k + 1 < NCHUNK) {
            asm volatile("cp.async.wait_group 1;" ::: "memory");
        } else {
            asm volatile("cp.async.wait_group 0;" ::: "memory");
        }
        __syncthreads();
        if (k + 2 < NCHUNK) {
            prefetch((k + 2) * BK_T, (k + 2) % NSTAGE);
            asm volatile("cp.async.commit_group;" ::: "memory");
        }

        const uint32_t* As32 = smem + (k % NSTAGE) * STAGE_WORDS;
        const uint32_t* Bs32 = As32 + A_WORDS;

        #pragma unroll
        for (int ks = 0; ks < 4; ks++) {
            uint32_t af[2][4];
            #pragma unroll
            for (int i = 0; i < 2; i++) {
                const uint32_t* ap = As32 + (wm * 32 + i * 16 + g) * STRIDE_W + ks * 8 + t;
                af[i][0] = ap[0];
                af[i][1] = ap[8 * STRIDE_W];
                af[i][2] = ap[4];
                af[i][3] = ap[8 * STRIDE_W + 4];
            }
            #pragma unroll
            for (int j = 0; j < 8; j++) {
                const uint32_t* bp = Bs32 + (wn * 64 + j * 8 + g) * STRIDE_W + ks * 8 + t;
                uint32_t b0 = bp[0];
                uint32_t b1 = bp[4];
                #pragma unroll
                for (int i = 0; i < 2; i++)
                    mma_f16(acc[i][j][0], acc[i][j][1], acc[i][j][2], acc[i][j][3],
                            af[i][0], af[i][1], af[i][2], af[i][3], b0, b1);
            }
        }
    }

    // ---- Epilogue: bias + leaky + gate, pre-LN store, per-row partials. ----
    // SMEM reuse (all warps past the last compute after this barrier):
    __syncthreads();
    float2* partial = (float2*)smem;            // [2][128] float2
    float2* sums    = (float2*)(smem + 512);    // [128] float2 (fixup stats)
    int*    flag    = (int*)(smem + 1024);

    #pragma unroll
    for (int i = 0; i < 2; i++) {
        #pragma unroll
        for (int half = 0; half < 2; half++) {
            const int rl = wm * 32 + i * 16 + half * 8 + g;
            const int m = bm + rl;
            const float* gate = g_cbuf + (size_t)(m & (N_DIM - 1)) * D_DIM;
            float* orow = out + (size_t)m * D_DIM;
            float s = 0.0f, ss = 0.0f;
            #pragma unroll
            for (int j = 0; j < 8; j++) {
                const int n = bn + wn * 64 + j * 8 + 2 * t;
                float2 bv = *(const float2*)(bias + n);
                float2 gv = *(const float2*)(gate + n);
                float v0 = acc[i][j][half * 2 + 0] + bv.x;
                float v1 = acc[i][j][half * 2 + 1] + bv.y;
                v0 = (v0 >= 0.0f) ? v0 : 0.2f * v0;
                v1 = (v1 >= 0.0f) ? v1 : 0.2f * v1;
                v0 *= gv.x;
                v1 *= gv.y;
                float2 o; o.x = v0; o.y = v1;
                *(float2*)(orow + n) = o;
                s += v0 + v1;
                ss += v0 * v0 + v1 * v1;
            }
            s  += __shfl_xor_sync(0xFFFFFFFFu, s, 1);
            ss += __shfl_xor_sync(0xFFFFFFFFu, ss, 1);
            s  += __shfl_xor_sync(0xFFFFFFFFu, s, 2);
            ss += __shfl_xor_sync(0xFFFFFFFFu, ss, 2);
            if (t == 0) {
                float2 p; p.x = s; p.y = ss;
                partial[wn * 128 + rl] = p;
            }
        }
    }
    __syncthreads();

    // Publish this CTA's per-row partial (its 128 columns), then signal.
    if (tid < 128) {
        float2 a = partial[tid];
        float2 b = partial[128 + tid];
        float2 p; p.x = a.x + b.x; p.y = a.y + b.y;
        g_part[((size_t)bmb * NBN + blockIdx.x) * 128 + tid] = p;
    }
    __threadfence();   // make out + g_part writes visible device-wide
    __syncthreads();
    if (tid == 0)
        *flag = atomicAdd(&g_cnt[bmb], 1);
    __syncthreads();
    if (*flag != NBN - 1)
        return;   // not the last CTA of this row-block

    // ---- Fixup (last CTA): stats + normalize the 128x1024 block. ----
    __threadfence();
    if (tid < 128) {
        float s = 0.0f, ss = 0.0f;
        const float2* pp = g_part + (size_t)bmb * NBN * 128 + tid;
        #pragma unroll
        for (int r = 0; r < NBN; r++) {   // fixed order -> deterministic
            float2 p = __ldcg(&pp[r * 128]);
            s += p.x; ss += p.y;
        }
        const float inv_d = 1.0f / (float)D_DIM;
        float mean = s * inv_d;
        float var  = ss * inv_d - mean * mean;
        float2 st; st.x = mean; st.y = rsqrtf(var + 1e-5f);
        sums[tid] = st;
    }
    if (tid == 0)
        g_cnt[bmb] = 0;   // reset for the next launch / graph replay
    __syncthreads();

    {
        float4 gm = *(const float4*)(gamma + tid * 4);
        float4 be = *(const float4*)(beta + tid * 4);
        float* ob = out + (size_t)bm * D_DIM + tid * 4;
        #pragma unroll 1
        for (int r = 0; r < BM_T; r += 4) {
            float4 v0 = __ldcg((const float4*)(ob + (size_t)(r + 0) * D_DIM));
            float4 v1 = __ldcg((const float4*)(ob + (size_t)(r + 1) * D_DIM));
            float4 v2 = __ldcg((const float4*)(ob + (size_t)(r + 2) * D_DIM));
            float4 v3 = __ldcg((const float4*)(ob + (size_t)(r + 3) * D_DIM));
            float2 s0 = sums[r + 0];
            float2 s1 = sums[r + 1];
            float2 s2 = sums[r + 2];
            float2 s3 = sums[r + 3];
            v0.x = (v0.x - s0.x) * s0.y * gm.x + be.x;
            v0.y = (v0.y - s0.x) * s0.y * gm.y + be.y;
            v0.z = (v0.z - s0.x) * s0.y * gm.z + be.z;
            v0.w = (v0.w - s0.x) * s0.y * gm.w + be.w;
            v1.x = (v1.x - s1.x) * s1.y * gm.x + be.x;
            v1.y = (v1.y - s1.x) * s1.y * gm.y + be.y;
            v1.z = (v1.z - s1.x) * s1.y * gm.z + be.z;
            v1.w = (v1.w - s1.x) * s1.y * gm.w + be.w;
            v2.x = (v2.x - s2.x) * s2.y * gm.x + be.x;
            v2.y = (v2.y - s2.x) * s2.y * gm.y + be.y;
            v2.z = (v2.z - s2.x) * s2.y * gm.z + be.z;
            v2.w = (v2.w - s2.x) * s2.y * gm.w + be.w;
            v3.x = (v3.x - s3.x) * s3.y * gm.x + be.x;
            v3.y = (v3.y - s3.x) * s3.y * gm.y + be.y;
            v3.z = (v3.z - s3.x) * s3.y * gm.z + be.z;
            v3.w = (v3.w - s3.x) * s3.y * gm.w + be.w;
            *(float4*)(ob + (size_t)(r + 0) * D_DIM) = v0;
            *(float4*)(ob + (size_t)(r + 1) * D_DIM) = v1;
            *(float4*)(ob + (size_t)(r + 2) * D_DIM) = v2;
            *(float4*)(ob + (size_t)(r + 3) * D_DIM) = v3;
        }
    }
}

// ---------------------------------------------------------------------------
extern "C" void kernel_launch(void* const* d_in, const int* in_sizes, int n_in,
                              void* d_out, int out_size)
{
    const float* input  = (const float*)d_in[0];  // [B, N, F]
    const float* stat   = (const float*)d_in[1];  // [N, K]
    const float* W_feat = (const float*)d_in[2];  // [D, F]
    const float* b_feat = (const float*)d_in[3];  // [D]
    const float* W_city = (const float*)d_in[4];  // [D, K]
    const float* b_city = (const float*)d_in[5];  // [D]
    const float* gamma  = (const float*)d_in[6];  // [D]
    const float* beta   = (const float*)d_in[7];  // [D]
    float* out = (float*)d_out;                   // [B, N, D]

    cudaFuncSetAttribute(main_gemm_fused,
                         cudaFuncAttributeMaxDynamicSharedMemorySize,
                         SMEM_BYTES);
    cudaFuncSetAttribute(city_gemm,
                         cudaFuncAttributeMaxDynamicSharedMemorySize,
                         SMEM_BYTES);

    __half *a16, *wf16, *st16, *wc16;
    cudaGetSymbolAddress((void**)&a16,  g_a16);
    cudaGetSymbolAddress((void**)&wf16, g_wf16);
    cudaGetSymbolAddress((void**)&st16, g_st16);
    cudaGetSymbolAddress((void**)&wc16, g_wc16);

    // 0) fp32 -> fp16 pre-passes
    {
        int n4 = (M_MAIN * F_DIM) / 4;   // 8388608
        f2h_kernel<<<(n4 + 1023) / 1024, 256>>>(input, a16, n4);
        int tot4 = WF_N4 + ST_N4 + WC_N4;  // 327680
        f2h3_kernel<<<(tot4 + 1023) / 1024, 256>>>(W_feat, wf16, stat, st16,
                                                   W_city, wc16);
    }
    // 1) city embed: g_cbuf = static @ W_city^T + b_city
    {
        dim3 grid(D_DIM / BN_T, N_DIM / BM_T);   // (8, 16)
        city_gemm<<<grid, 256, SMEM_BYTES>>>(st16, wc16, b_city);
    }
    // 2) main fused: GEMM + gate + stream-K LayerNorm fixup
    {
        dim3 grid(NBN, NBM);   // (8, 512)
        main_gemm_fused<<<grid, 256, SMEM_BYTES>>>(a16, wf16, b_feat,
                                                   gamma, beta, out);
    }
}

// round 16
// speedup vs baseline: 2.5606x; 1.0944x over previous
#include <cuda_runtime.h>
#include <cuda_fp16.h>
#include <cstdint>

// Problem constants
#define B_DIM 32
#define N_DIM 2048
#define F_DIM 512
#define K_DIM 256
#define D_DIM 1024
#define M_MAIN (B_DIM * N_DIM)   // 65536

// __device__ scratch (no cudaMalloc allowed anywhere).
__device__ float  g_cbuf[N_DIM * D_DIM];   // city embedding c[N, D]   (8 MB)
__device__ __half g_a16[M_MAIN * F_DIM];   // fp16 input               (64 MB)
__device__ __half g_pre[M_MAIN * D_DIM];   // fp16 pre-LN staging      (128 MB)
__device__ __half g_wf16[D_DIM * F_DIM];   // fp16 W_feat              (1 MB)
__device__ __half g_st16[N_DIM * K_DIM];   // fp16 static              (1 MB)
__device__ __half g_wc16[D_DIM * K_DIM];   // fp16 W_city              (0.5 MB)

// ---------------------------------------------------------------------------
// helpers
// ---------------------------------------------------------------------------
__device__ __forceinline__ uint32_t smem_u32(const void* p) {
    uint32_t a;
    asm("{ .reg .u64 t; cvta.to.shared.u64 t, %1; cvt.u32.u64 %0, t; }"
        : "=r"(a) : "l"(p));
    return a;
}

__device__ __forceinline__ void cp_async16(uint32_t dst, const void* src) {
    asm volatile("cp.async.cg.shared.global [%0], [%1], 16;"
                 :: "r"(dst), "l"(src) : "memory");
}

__device__ __forceinline__ void mma_f16(float& c0, float& c1, float& c2, float& c3,
                                        uint32_t a0, uint32_t a1, uint32_t a2, uint32_t a3,
                                        uint32_t b0, uint32_t b1) {
    asm volatile(
        "mma.sync.aligned.m16n8k16.row.col.f32.f16.f16.f32 "
        "{%0,%1,%2,%3}, {%4,%5,%6,%7}, {%8,%9}, {%0,%1,%2,%3};"
        : "+f"(c0), "+f"(c1), "+f"(c2), "+f"(c3)
        : "r"(a0), "r"(a1), "r"(a2), "r"(a3), "r"(b0), "r"(b1));
}

// ---------------------------------------------------------------------------
// Merged fp32 -> fp16 prepass: input + all three weight tensors, one launch.
// ---------------------------------------------------------------------------
#define IN_N4 (M_MAIN * F_DIM / 4)  // 8388608
#define WF_N4 (D_DIM * F_DIM / 4)   // 131072
#define ST_N4 (N_DIM * K_DIM / 4)   // 131072
#define WC_N4 (D_DIM * K_DIM / 4)   // 65536
#define PRE_TOT4 (IN_N4 + WF_N4 + ST_N4 + WC_N4)  // 8716288 (= 8512 * 1024)

__global__ __launch_bounds__(256) void prepass_kernel(
    const float* __restrict__ in,  const float* __restrict__ wf,
    const float* __restrict__ st,  const float* __restrict__ wc)
{
    int i = blockIdx.x * 1024 + threadIdx.x;
    #pragma unroll
    for (int s = 0; s < 4; s++) {
        int idx = i + s * 256;
        const float* src; __half* dst; int off;
        if (idx < IN_N4)                       { src = in; dst = g_a16;  off = idx; }
        else if (idx < IN_N4 + WF_N4)          { src = wf; dst = g_wf16; off = idx - IN_N4; }
        else if (idx < IN_N4 + WF_N4 + ST_N4)  { src = st; dst = g_st16; off = idx - IN_N4 - WF_N4; }
        else if (idx < PRE_TOT4)               { src = wc; dst = g_wc16; off = idx - IN_N4 - WF_N4 - ST_N4; }
        else continue;
        float4 v = ((const float4*)src)[off];
        __half2 h0 = __floats2half2_rn(v.x, v.y);
        __half2 h1 = __floats2half2_rn(v.z, v.w);
        uint2 u;
        u.x = *(uint32_t*)&h0;
        u.y = *(uint32_t*)&h1;
        ((uint2*)dst)[off] = u;
    }
}

// ---------------------------------------------------------------------------
// Tiling constants (fp16 operands, fp32 accum); 36-word SMEM row stride
// -> conflict-free fragment LDS.
// ---------------------------------------------------------------------------
#define BM_T 128
#define BN_T 128
#define BK_T 64
#define STRIDE_W 36
#define A_WORDS (BM_T * STRIDE_W)            // 4608
#define B_WORDS (BN_T * STRIDE_W)            // 4608
#define STAGE_WORDS (A_WORDS + B_WORDS)      // 9216
#define NSTAGE 3
#define SMEM_BYTES (NSTAGE * STAGE_WORDS * 4)  // 110592

// ---------------------------------------------------------------------------
// City GEMM (fp16 mma): g_cbuf[m*D + n] = static @ W_city^T + b_city  (fp32)
// ---------------------------------------------------------------------------
__global__ __launch_bounds__(256, 2) void city_gemm(
    const float* __restrict__ bias)  // [D_DIM]
{
    constexpr int KD = K_DIM;
    constexpr int NCHUNK = KD / BK_T;   // 4

    extern __shared__ uint32_t smem[];
    const int tid  = threadIdx.x;
    const int wid  = tid >> 5;
    const int lane = tid & 31;
    const int wm   = wid & 3;
    const int wn   = wid >> 2;
    const int g    = lane >> 2;
    const int t    = lane & 3;

    const int bm = blockIdx.y * BM_T;
    const int bn = blockIdx.x * BN_T;

    const __half* Arow = g_st16 + (size_t)bm * KD;
    const __half* Wrow = g_wc16 + (size_t)bn * KD;
    const uint32_t smem_b = smem_u32(smem);

    float acc[2][8][4];
    #pragma unroll
    for (int i = 0; i < 2; i++)
        #pragma unroll
        for (int j = 0; j < 8; j++)
            #pragma unroll
            for (int c = 0; c < 4; c++) acc[i][j][c] = 0.0f;

    auto prefetch = [&](int k0, int buf) {
        const uint32_t a_s = smem_b + (uint32_t)(buf * STAGE_WORDS) * 4u;
        const uint32_t b_s = a_s + A_WORDS * 4u;
        #pragma unroll
        for (int s = 0; s < 4; s++) {
            int id = tid + s * 256;
            int r  = id >> 3;
            int c16 = id & 7;
            cp_async16(a_s + (uint32_t)(r * 144 + c16 * 16),
                       Arow + (size_t)r * KD + k0 + c16 * 8);
        }
        #pragma unroll
        for (int s = 0; s < 4; s++) {
            int id = tid + s * 256;
            int r  = id >> 3;
            int c16 = id & 7;
            cp_async16(b_s + (uint32_t)(r * 144 + c16 * 16),
                       Wrow + (size_t)r * KD + k0 + c16 * 8);
        }
    };

    prefetch(0, 0);
    asm volatile("cp.async.commit_group;" ::: "memory");
    prefetch(BK_T, 1);
    asm volatile("cp.async.commit_group;" ::: "memory");

    #pragma unroll
    for (int k = 0; k < NCHUNK; k++) {
        if (k + 1 < NCHUNK) {
            asm volatile("cp.async.wait_group 1;" ::: "memory");
        } else {
            asm volatile("cp.async.wait_group 0;" ::: "memory");
        }
        __syncthreads();
        if (k + 2 < NCHUNK) {
            prefetch((k + 2) * BK_T, (k + 2) % NSTAGE);
            asm volatile("cp.async.commit_group;" ::: "memory");
        }

        const uint32_t* As32 = smem + (k % NSTAGE) * STAGE_WORDS;
        const uint32_t* Bs32 = As32 + A_WORDS;

        #pragma unroll
        for (int ks = 0; ks < 4; ks++) {
            uint32_t af[2][4];
            #pragma unroll
            for (int i = 0; i < 2; i++) {
                const uint32_t* ap = As32 + (wm * 32 + i * 16 + g) * STRIDE_W + ks * 8 + t;
                af[i][0] = ap[0];
                af[i][1] = ap[8 * STRIDE_W];
                af[i][2] = ap[4];
                af[i][3] = ap[8 * STRIDE_W + 4];
            }
            #pragma unroll
            for (int j = 0; j < 8; j++) {
                const uint32_t* bp = Bs32 + (wn * 64 + j * 8 + g) * STRIDE_W + ks * 8 + t;
                uint32_t b0 = bp[0];
                uint32_t b1 = bp[4];
                #pragma unroll
                for (int i = 0; i < 2; i++)
                    mma_f16(acc[i][j][0], acc[i][j][1], acc[i][j][2], acc[i][j][3],
                            af[i][0], af[i][1], af[i][2], af[i][3], b0, b1);
            }
        }
    }

    #pragma unroll
    for (int i = 0; i < 2; i++) {
        #pragma unroll
        for (int half = 0; half < 2; half++) {
            const int m = bm + wm * 32 + i * 16 + half * 8 + g;
            float* orow = g_cbuf + (size_t)m * D_DIM;
            #pragma unroll
            for (int j = 0; j < 8; j++) {
                const int n = bn + wn * 64 + j * 8 + 2 * t;
                float2 bv = *(const float2*)(bias + n);
                float2 o;
                o.x = acc[i][j][half * 2 + 0] + bv.x;
                o.y = acc[i][j][half * 2 + 1] + bv.y;
                *(float2*)(orow + n) = o;
            }
        }
    }
}

// ---------------------------------------------------------------------------
// Main GEMM (fp16 mma): g_pre[m*D + n] = fp16(leaky(input @ W_feat^T + bias))
// Lean epilogue: no gate loads, fp16 stores (64 MB instead of 256 MB).
// ---------------------------------------------------------------------------
__global__ __launch_bounds__(256, 2) void main_gemm(
    const float* __restrict__ bias)  // [D_DIM]
{
    constexpr int KD = F_DIM;
    constexpr int NCHUNK = KD / BK_T;   // 8

    extern __shared__ uint32_t smem[];
    const int tid  = threadIdx.x;
    const int wid  = tid >> 5;
    const int lane = tid & 31;
    const int wm   = wid & 3;
    const int wn   = wid >> 2;
    const int g    = lane >> 2;
    const int t    = lane & 3;

    const int bm = blockIdx.y * BM_T;
    const int bn = blockIdx.x * BN_T;

    const __half* Arow = g_a16 + (size_t)bm * KD;
    const __half* Wrow = g_wf16 + (size_t)bn * KD;
    const uint32_t smem_b = smem_u32(smem);

    float acc[2][8][4];
    #pragma unroll
    for (int i = 0; i < 2; i++)
        #pragma unroll
        for (int j = 0; j < 8; j++)
            #pragma unroll
            for (int c = 0; c < 4; c++) acc[i][j][c] = 0.0f;

    auto prefetch = [&](int k0, int buf) {
        const uint32_t a_s = smem_b + (uint32_t)(buf * STAGE_WORDS) * 4u;
        const uint32_t b_s = a_s + A_WORDS * 4u;
        #pragma unroll
        for (int s = 0; s < 4; s++) {
            int id = tid + s * 256;
            int r  = id >> 3;
            int c16 = id & 7;
            cp_async16(a_s + (uint32_t)(r * 144 + c16 * 16),
                       Arow + (size_t)r * KD + k0 + c16 * 8);
        }
        #pragma unroll
        for (int s = 0; s < 4; s++) {
            int id = tid + s * 256;
            int r  = id >> 3;
            int c16 = id & 7;
            cp_async16(b_s + (uint32_t)(r * 144 + c16 * 16),
                       Wrow + (size_t)r * KD + k0 + c16 * 8);
        }
    };

    prefetch(0, 0);
    asm volatile("cp.async.commit_group;" ::: "memory");
    prefetch(BK_T, 1);
    asm volatile("cp.async.commit_group;" ::: "memory");

    #pragma unroll
    for (int k = 0; k < NCHUNK; k++) {
        if (k + 1 < NCHUNK) {
            asm volatile("cp.async.wait_group 1;" ::: "memory");
        } else {
            asm volatile("cp.async.wait_group 0;" ::: "memory");
        }
        __syncthreads();
        if (k + 2 < NCHUNK) {
            prefetch((k + 2) * BK_T, (k + 2) % NSTAGE);
            asm volatile("cp.async.commit_group;" ::: "memory");
        }

        const uint32_t* As32 = smem + (k % NSTAGE) * STAGE_WORDS;
        const uint32_t* Bs32 = As32 + A_WORDS;

        #pragma unroll
        for (int ks = 0; ks < 4; ks++) {
            uint32_t af[2][4];
            #pragma unroll
            for (int i = 0; i < 2; i++) {
                const uint32_t* ap = As32 + (wm * 32 + i * 16 + g) * STRIDE_W + ks * 8 + t;
                af[i][0] = ap[0];
                af[i][1] = ap[8 * STRIDE_W];
                af[i][2] = ap[4];
                af[i][3] = ap[8 * STRIDE_W + 4];
            }
            #pragma unroll
            for (int j = 0; j < 8; j++) {
                const uint32_t* bp = Bs32 + (wn * 64 + j * 8 + g) * STRIDE_W + ks * 8 + t;
                uint32_t b0 = bp[0];
                uint32_t b1 = bp[4];
                #pragma unroll
                for (int i = 0; i < 2; i++)
                    mma_f16(acc[i][j][0], acc[i][j][1], acc[i][j][2], acc[i][j][3],
                            af[i][0], af[i][1], af[i][2], af[i][3], b0, b1);
            }
        }
    }

    // Epilogue: bias + leaky -> fp16 -> g_pre
    #pragma unroll
    for (int i = 0; i < 2; i++) {
        #pragma unroll
        for (int half = 0; half < 2; half++) {
            const int m = bm + wm * 32 + i * 16 + half * 8 + g;
            __half* orow = g_pre + (size_t)m * D_DIM;
            #pragma unroll
            for (int j = 0; j < 8; j++) {
                const int n = bn + wn * 64 + j * 8 + 2 * t;
                float2 bv = *(const float2*)(bias + n);
                float v0 = acc[i][j][half * 2 + 0] + bv.x;
                float v1 = acc[i][j][half * 2 + 1] + bv.y;
                v0 = (v0 >= 0.0f) ? v0 : 0.2f * v0;
                v1 = (v1 >= 0.0f) ? v1 : 0.2f * v1;
                *(__half2*)(orow + n) = __floats2half2_rn(v0, v1);
            }
        }
    }
}

// ---------------------------------------------------------------------------
// Final LN: y = LN(pre_fp16 * gate) * gamma + beta.
// One block per row, 256 threads; pre read fp16 (128 MB), gate from L2-hot
// g_cbuf, final fp32 write. Stats computed on exactly the normalized values.
// ---------------------------------------------------------------------------
__global__ __launch_bounds__(256) void ln_final(
    const float* __restrict__ gamma, const float* __restrict__ beta,
    float* __restrict__ out)
{
    __shared__ float red_s[8];
    __shared__ float red_ss[8];

    const size_t row = blockIdx.x;
    const size_t nrow = row & (N_DIM - 1);
    const int tid = threadIdx.x;

    uint2 u = ((const uint2*)(g_pre + row * D_DIM))[tid];     // 4 halves
    float4 c = ((const float4*)(g_cbuf + nrow * D_DIM))[tid]; // gate
    float2 f0 = __half22float2(*(__half2*)&u.x);
    float2 f1 = __half22float2(*(__half2*)&u.y);
    float4 v;
    v.x = f0.x * c.x; v.y = f0.y * c.y;
    v.z = f1.x * c.z; v.w = f1.y * c.w;

    float s  = v.x + v.y + v.z + v.w;
    float ss = v.x * v.x + v.y * v.y + v.z * v.z + v.w * v.w;

    #pragma unroll
    for (int o = 16; o > 0; o >>= 1) {
        s  += __shfl_xor_sync(0xFFFFFFFFu, s,  o);
        ss += __shfl_xor_sync(0xFFFFFFFFu, ss, o);
    }
    const int wid = tid >> 5, lid = tid & 31;
    if (lid == 0) { red_s[wid] = s; red_ss[wid] = ss; }
    __syncthreads();

    s = 0.0f; ss = 0.0f;
    #pragma unroll
    for (int w = 0; w < 8; w++) { s += red_s[w]; ss += red_ss[w]; }

    const float inv_d = 1.0f / (float)D_DIM;
    float mean = s * inv_d;
    float var  = ss * inv_d - mean * mean;
    float rstd = rsqrtf(var + 1e-5f);

    float4 gm = ((const float4*)gamma)[tid];
    float4 be = ((const float4*)beta)[tid];
    v.x = (v.x - mean) * rstd * gm.x + be.x;
    v.y = (v.y - mean) * rstd * gm.y + be.y;
    v.z = (v.z - mean) * rstd * gm.z + be.z;
    v.w = (v.w - mean) * rstd * gm.w + be.w;
    ((float4*)(out + row * D_DIM))[tid] = v;
}

// ---------------------------------------------------------------------------
extern "C" void kernel_launch(void* const* d_in, const int* in_sizes, int n_in,
                              void* d_out, int out_size)
{
    const float* input  = (const float*)d_in[0];  // [B, N, F]
    const float* stat   = (const float*)d_in[1];  // [N, K]
    const float* W_feat = (const float*)d_in[2];  // [D, F]
    const float* b_feat = (const float*)d_in[3];  // [D]
    const float* W_city = (const float*)d_in[4];  // [D, K]
    const float* b_city = (const float*)d_in[5];  // [D]
    const float* gamma  = (const float*)d_in[6];  // [D]
    const float* beta   = (const float*)d_in[7];  // [D]
    float* out = (float*)d_out;                   // [B, N, D]

    cudaFuncSetAttribute(main_gemm,
                         cudaFuncAttributeMaxDynamicSharedMemorySize, SMEM_BYTES);
    cudaFuncSetAttribute(city_gemm,
                         cudaFuncAttributeMaxDynamicSharedMemorySize, SMEM_BYTES);

    // 0) merged fp32 -> fp16 prepass (input + all weights)
    prepass_kernel<<<PRE_TOT4 / 1024, 256>>>(input, W_feat, stat, W_city);

    // 1) main embed GEMM: g_pre = fp16(leaky(input @ W_feat^T + b_feat))
    {
        dim3 grid(D_DIM / BN_T, M_MAIN / BM_T);  // (8, 512)
        main_gemm<<<grid, 256, SMEM_BYTES>>>(b_feat);
    }
    // 2) city embed GEMM: g_cbuf = static @ W_city^T + b_city
    {
        dim3 grid(D_DIM / BN_T, N_DIM / BM_T);   // (8, 16)
        city_gemm<<<grid, 256, SMEM_BYTES>>>(b_city);
    }
    // 3) final: out = LN(g_pre * g_cbuf) * gamma + beta
    ln_final<<<M_MAIN, 256>>>(gamma, beta, out);
}